// round 13
// baseline (speedup 1.0000x reference)
#include <cuda_runtime.h>
#include <cstdint>

#define NB   64
#define NPG  1024
#define NFEA 8
#define MIN_DIST 2.9f

#define TILE     128
#define NCHUNK   (NPG / TILE)                  // 8
#define NTRI     (NCHUNK * (NCHUNK + 1) / 2)   // 36
#define CTHREADS 256
#define NBLOCKS  ((NTRI + 1) * NB)             // 2368
#define JSLICE   16

typedef unsigned long long u64;

// triangle tile decode tables (ic >= jc)
__device__ const signed char TIC[NTRI] =
    {0,1,1,2,2,2,3,3,3,3,4,4,4,4,4,5,5,5,5,5,5,
     6,6,6,6,6,6,6,7,7,7,7,7,7,7,7};
__device__ const signed char TJC[NTRI] =
    {0,0,1,0,1,2,0,1,2,3,0,1,2,3,4,0,1,2,3,4,5,
     0,1,2,3,4,5,6,0,1,2,3,4,5,6,7};

// sorted points per batch: (x, y, z, |p|^2), ascending x
__device__ float4 g_pts[NB * NPG];

// partial slots — fully overwritten every launch (skipped tiles write 0)
__device__ float g_coll[NTRI * NB];      // 2304
__device__ float g_sb[NB][8];
__device__ unsigned int g_done = 0;

// ---------------- reduce helpers ----------------
__device__ __forceinline__ float wredSum(float v) {
#pragma unroll
    for (int o = 16; o; o >>= 1) v += __shfl_down_sync(0xffffffffu, v, o);
    return v;
}
__device__ __forceinline__ float wredMin(float v) {
#pragma unroll
    for (int o = 16; o; o >>= 1) v = fminf(v, __shfl_down_sync(0xffffffffu, v, o));
    return v;
}
__device__ __forceinline__ float wredMax(float v) {
#pragma unroll
    for (int o = 16; o; o >>= 1) v = fmaxf(v, __shfl_down_sync(0xffffffffu, v, o));
    return v;
}
__device__ __forceinline__ float blockSum(float v, float* sbuf) {
    const int lane = threadIdx.x & 31;
    const int wid  = threadIdx.x >> 5;
    v = wredSum(v);
    if (lane == 0) sbuf[wid] = v;
    __syncthreads();
    if (wid == 0) {
        v = (lane < 8) ? sbuf[lane] : 0.0f;
        v = wredSum(v);
        if (lane == 0) sbuf[0] = v;
    }
    __syncthreads();
    float r = sbuf[0];
    __syncthreads();
    return r;
}
__device__ __forceinline__ double blockSumD(double v, double* dbuf) {
    const int lane = threadIdx.x & 31;
    const int wid  = threadIdx.x >> 5;
#pragma unroll
    for (int o = 16; o; o >>= 1) v += __shfl_down_sync(0xffffffffu, v, o);
    if (lane == 0) dbuf[wid] = v;
    __syncthreads();
    if (wid == 0) {
        v = (lane < 8) ? dbuf[lane] : 0.0;
#pragma unroll
        for (int o = 16; o; o >>= 1) v += __shfl_down_sync(0xffffffffu, v, o);
        if (lane == 0) dbuf[0] = v;
    }
    __syncthreads();
    double r = dbuf[0];
    __syncthreads();
    return r;
}
__device__ __forceinline__ float sqrt_approx(float x) {
    float d; asm("sqrt.approx.f32 %0,%1;" : "=f"(d) : "f"(x)); return d;
}

// ---------------- sort kernel: per-batch bitonic, 512 threads (1 CE each) ----
__global__ __launch_bounds__(512) void k_sort(const float* __restrict__ pred)
{
    __shared__ u64 skey[NPG];
    const int b = blockIdx.x;
    const int t = threadIdx.x;

#pragma unroll
    for (int k = 0; k < 2; k++) {
        const int idx = t + k * 512;
        const float x = pred[3 * (size_t)(b * NPG + idx)];
        unsigned int u = __float_as_uint(x);
        u = (u >> 31) ? ~u : (u | 0x80000000u);
        skey[idx] = ((u64)u << 32) | (unsigned)idx;
    }
    __syncthreads();

    for (unsigned int ks = 2; ks <= NPG; ks <<= 1) {
        for (unsigned int j = ks >> 1; j > 0; j >>= 1) {
            // 1 compare-exchange per thread
            const unsigned int lo = ((t & ~(j - 1u)) << 1) | (t & (j - 1u));
            const unsigned int hi = lo | j;
            const u64 a = skey[lo];
            const u64 c = skey[hi];
            const bool up = ((lo & ks) == 0);
            if ((a > c) == up) { skey[lo] = c; skey[hi] = a; }
            __syncthreads();
        }
    }

    // gather sorted points, precompute |p|^2
#pragma unroll
    for (int k = 0; k < 2; k++) {
        const int idx = t + k * 512;
        const int id  = (int)(skey[idx] & 0xFFFFFFFFu);
        const float* p = pred + 3 * (size_t)(b * NPG + id);
        const float x = p[0], y = p[1], z = p[2];
        g_pts[b * NPG + idx] = make_float4(x, y, z, fmaf(x, x, fmaf(y, y, z * z)));
    }
}

// ---------------- fused kernel (R9 structure + per-warp slice prune) --------
// grid (NTRI+1, NB), 256 threads.
__global__ __launch_bounds__(CTHREADS) void k_fused(
    const float* __restrict__ pred,
    const float* __restrict__ tru,
    const float* __restrict__ org,
    const float* __restrict__ nfeat,
    float* __restrict__ out, int out_size)
{
    __shared__ float4 sj[TILE];
    __shared__ float  sred[8];
    __shared__ float  sq[16][8];
    __shared__ double dbuf[8];
    __shared__ bool   amLast;

    const int b  = blockIdx.y;
    const int bx = blockIdx.x;
    const int t  = threadIdx.x;
    const int lane = t & 31;
    const int wid  = t >> 5;

    if (bx < NTRI) {
        const int ic = TIC[bx];
        const int jc = TJC[bx];
        const float4* __restrict__ P = g_pts + (size_t)b * NPG;
        const int ibase = ic * TILE;
        const int jbase = jc * TILE;

        // block-level exact prune (sorted x): whole tile-pair has gap >= 2.9
        const bool skip = (ic != jc) &&
                          (P[ibase].x - P[jbase + TILE - 1].x >= MIN_DIST);

        float S = 0.0f;
        if (!skip) {
            if (t < TILE) sj[t] = P[jbase + t];

            const int r   = lane;
            const int jlo = wid * JSLICE;

            float m2x[4], m2y[4], m2z[4], si[4];
#pragma unroll
            for (int k = 0; k < 4; k++) {
                const float4 pi = P[ibase + r + 32 * k];
                si[k]  = pi.w;
                m2x[k] = -2.0f * pi.x;
                m2y[k] = -2.0f * pi.y;
                m2z[k] = -2.0f * pi.z;
            }
            __syncthreads();

            // per-warp slice prune: if this warp's j-slice [jlo, jlo+16) is
            // entirely >= 2.9 below the i-tile's min x, every pair in the
            // slice has d >= dx >= 2.9 -> contributes exactly 0.  Warp-uniform.
            // (A slice containing a thread's own self-row can never satisfy
            // this: that row's x is in both ranges -> gap <= 0.)
            const bool wskip = (P[ibase].x - sj[jlo + JSLICE - 1].x >= MIN_DIST);

            float a = 0.0f;
            if (!wskip) {
                float acc[4] = {0.0f, 0.0f, 0.0f, 0.0f};
#pragma unroll
                for (int m = 0; m < JSLICE; m++) {
                    const float4 q = sj[jlo + m];
#pragma unroll
                    for (int k = 0; k < 4; k++) {
                        const float d2 = fmaf(m2x[k], q.x,
                                         fmaf(m2y[k], q.y,
                                         fmaf(m2z[k], q.z, si[k] + q.w)));
                        const float d  = sqrt_approx(d2);   // d2<0 -> NaN -> relu 0
                        const float e  = fmaxf(MIN_DIST - d, 0.0f);
                        acc[k] = fmaf(e, e, acc[k]);
                    }
                }
                a = (acc[0] + acc[1]) + (acc[2] + acc[3]);

                // diagonal: remove self-pairs (identical instruction sequence)
                if (ic == jc) {
#pragma unroll
                    for (int k = 0; k < 4; k++) {
                        const int i  = r + 32 * k;
                        const int jd = i - jlo;
                        if (jd >= 0 && jd < JSLICE) {
                            const float4 q = sj[i];
                            const float d2 = fmaf(m2x[k], q.x,
                                             fmaf(m2y[k], q.y,
                                             fmaf(m2z[k], q.z, si[k] + q.w)));
                            const float d  = sqrt_approx(d2);
                            const float e  = fmaxf(MIN_DIST - d, 0.0f);
                            a = fmaf(-e, e, a);
                        }
                    }
                }
            }

            S = blockSum(a, sred);
        }
        if (t == 0)
            g_coll[b * NTRI + bx] = skip ? 0.0f : ((ic != jc) ? 2.0f * S : S);
    } else {
        // ======================= stats =======================
        float px[4], py[4], pz[4], ox[4], oy[4], oz[4];
        float rsum = 0.0f;
#pragma unroll
        for (int k = 0; k < 4; k++) {
            const int idx = b * NPG + t + k * 256;
            const float* pp = pred + 3 * idx;
            const float* tt = tru  + 3 * idx;
            const float* oo = org  + 3 * idx;
            px[k] = pp[0]; py[k] = pp[1]; pz[k] = pp[2];
            const float dx = px[k] - tt[0];
            const float dy = py[k] - tt[1];
            const float dz = pz[k] - tt[2];
            rsum += dx * dx + dy * dy + dz * dz;
            ox[k] = oo[0]; oy[k] = oo[1]; oz[k] = oo[2];
        }

        float lv[14];
        lv[0]  = fminf(fminf(px[0], px[1]), fminf(px[2], px[3]));
        lv[1]  = fmaxf(fmaxf(px[0], px[1]), fmaxf(px[2], px[3]));
        lv[2]  = fminf(fminf(py[0], py[1]), fminf(py[2], py[3]));
        lv[3]  = fmaxf(fmaxf(py[0], py[1]), fmaxf(py[2], py[3]));
        lv[4]  = fminf(fminf(pz[0], pz[1]), fminf(pz[2], pz[3]));
        lv[5]  = fmaxf(fmaxf(pz[0], pz[1]), fmaxf(pz[2], pz[3]));
        lv[6]  = fminf(fminf(ox[0], ox[1]), fminf(ox[2], ox[3]));
        lv[7]  = fmaxf(fmaxf(ox[0], ox[1]), fmaxf(ox[2], ox[3]));
        lv[8]  = fminf(fminf(oy[0], oy[1]), fminf(oy[2], oy[3]));
        lv[9]  = fmaxf(fmaxf(oy[0], oy[1]), fmaxf(oy[2], oy[3]));
        lv[10] = fminf(fminf(oz[0], oz[1]), fminf(oz[2], oz[3]));
        lv[11] = fmaxf(fmaxf(oz[0], oz[1]), fmaxf(oz[2], oz[3]));
        lv[12] = pz[0] + pz[1] + pz[2] + pz[3];
        lv[13] = rsum;

#pragma unroll
        for (int i = 0; i < 14; i++) {
            float v;
            if (i < 12) v = (i & 1) ? wredMax(lv[i]) : wredMin(lv[i]);
            else        v = wredSum(lv[i]);
            if (lane == 0) sq[i][wid] = v;
        }
        __syncthreads();
        if (t < 14) {
            float a = sq[t][0];
            const bool isMin = (t < 12) && !(t & 1);
            const bool isMax = (t < 12) &&  (t & 1);
#pragma unroll
            for (int w = 1; w < 8; w++) {
                const float u = sq[t][w];
                a = isMin ? fminf(a, u) : (isMax ? fmaxf(a, u) : (a + u));
            }
            sq[t][0] = a;
        }
        __syncthreads();

        const float OMNZ = sq[10][0], OMXZ = sq[11][0];
        const float zr   = __fsub_rn(OMXZ, OMNZ);
        const float thlo = __fadd_rn(OMNZ, __fmul_rn(0.15f, zr));
        const float thhi = __fsub_rn(OMXZ, __fmul_rn(0.15f, zr));

        float esum = 0.0f, ecnt = 0.0f;
#pragma unroll
        for (int k = 0; k < 4; k++) {
            const bool m = (oz[k] <= thlo) || (oz[k] >= thhi);
            if (m) {
                const float dx = px[k] - ox[k];
                const float dy = py[k] - oy[k];
                const float dz = pz[k] - oz[k];
                esum += dx * dx + dy * dy + dz * dz;
                ecnt += 1.0f;
            }
        }
        esum = wredSum(esum);
        ecnt = wredSum(ecnt);
        if (lane == 0) { sq[14][wid] = esum; sq[15][wid] = ecnt; }
        __syncthreads();

        if (t == 0) {
            float ES = 0.0f, EC = 0.0f;
#pragma unroll
            for (int w = 0; w < 8; w++) { ES += sq[14][w]; EC += sq[15][w]; }

            const float pdx = sq[1][0] - sq[0][0];
            const float pdy = sq[3][0] - sq[2][0];
            const float pdz = sq[5][0] - sq[4][0];
            const float odx = sq[7][0] - sq[6][0];
            const float ody = sq[9][0] - sq[8][0];
            const float odz = OMXZ - OMNZ;
            const float rx = (pdx - odx) / (odx + 1e-8f);
            const float ry = (pdy - ody) / (ody + 1e-8f);
            const float rz = (pdz - odz) / (odz + 1e-8f);
            const float xy_pen = fmaxf(rx - 0.02f, 0.0f) + fmaxf(ry - 0.02f, 0.0f);
            const float z_pen  = fmaxf(rz, 0.0f);

            const float zcom  = sq[12][0] * (1.0f / 1024.0f);
            const float znorm = (zcom - sq[4][0]) / ((sq[5][0] - sq[4][0]) + 1e-8f);
            const float v = nfeat[(size_t)b * NPG * NFEA + (NFEA - 3)];
            const float target = (v > 0.0f) ? 0.6f : 0.4f;
            const float dvz = znorm - target;
            const float contrib = (fabsf(v) >= 1e-6f) ? dvz * dvz : 0.0f;

            g_sb[b][0] = sq[13][0];
            g_sb[b][1] = ES;
            g_sb[b][2] = EC;
            g_sb[b][3] = xy_pen + 2.0f * z_pen;
            g_sb[b][4] = contrib;
        }
        __syncthreads();
    }

    // ======================= last-block finalize =======================
    __threadfence();
    if (t == 0) {
        const unsigned int ret = atomicAdd(&g_done, 1u);
        amLast = (ret == (unsigned)(NBLOCKS - 1));
    }
    __syncthreads();

    if (amLast) {
        __threadfence();

        double cs = 0.0;
#pragma unroll
        for (int k = 0; k < 9; k++) cs += (double)g_coll[t + k * 256];   // 2304
        const double COLL = blockSumD(cs, dbuf);

        double r = 0.0, e = 0.0, c = 0.0, vo = 0.0, f = 0.0;
        if (t < NB) {
            r  = (double)g_sb[t][0];
            e  = (double)g_sb[t][1];
            c  = (double)g_sb[t][2];
            vo = (double)g_sb[t][3];
            f  = (double)g_sb[t][4];
        }
        const double RSUM = blockSumD(r,  dbuf);
        const double ESUM = blockSumD(e,  dbuf);
        const double ECNT = blockSumD(c,  dbuf);
        const double VSUM = blockSumD(vo, dbuf);
        const double FSUM = blockSumD(f,  dbuf);

        if (t == 0) {
            const double recon  = RSUM / (double)(NB * NPG * 3);
            const double volume = VSUM / (double)NB;
            const double elec   = ESUM / (ECNT * 3.0);
            const double coll   = COLL / ((double)NB * (double)NPG * (double)(NPG - 1));
            const double field  = FSUM / (double)NB;
            const double total  = 1.0 * recon + 10.0 * volume + 50.0 * elec
                                + 5.0 * coll + 2.0 * field;
            double vals[6] = { total, recon, volume, elec, coll, field };
            for (int i = 0; i < 6 && i < out_size; i++) out[i] = (float)vals[i];
            g_done = 0;   // reset for next graph replay
        }
    }
}

extern "C" void kernel_launch(void* const* d_in, const int* in_sizes, int n_in,
                              void* d_out, int out_size)
{
    int coord_idx[3]; int n_coord = 0;
    int nf_idx = -1, bv_idx = -1;
    for (int i = 0; i < n_in; i++) {
        if (in_sizes[i] == NB * NPG * 3) { if (n_coord < 3) coord_idx[n_coord] = i; n_coord++; }
        else if (in_sizes[i] == NB * NPG * NFEA) nf_idx = i;
        else if (in_sizes[i] == NB * NPG) bv_idx = i;
    }

    const float *pred, *tru, *org, *nf;
    if (n_coord == 3 && nf_idx >= 0) {
        if (bv_idx >= 0 && bv_idx < coord_idx[0]) {
            org  = (const float*)d_in[coord_idx[0]];
            pred = (const float*)d_in[coord_idx[1]];
            tru  = (const float*)d_in[coord_idx[2]];
        } else {
            pred = (const float*)d_in[coord_idx[0]];
            tru  = (const float*)d_in[coord_idx[1]];
            org  = (const float*)d_in[coord_idx[2]];
        }
        nf = (const float*)d_in[nf_idx];
    } else {
        pred = (const float*)d_in[0];
        tru  = (const float*)d_in[1];
        org  = (const float*)d_in[2];
        nf   = (const float*)d_in[3];
    }

    k_sort<<<NB, 512>>>(pred);
    k_fused<<<dim3(NTRI + 1, NB), CTHREADS>>>(pred, tru, org, nf,
                                              (float*)d_out, out_size);
}

// round 14
// speedup vs baseline: 1.1648x; 1.1648x over previous
#include <cuda_runtime.h>
#include <cstdint>

#define NB   64
#define NPG  1024
#define NFEA 8
#define MIN_DIST 2.9f

#define TILE     128
#define NCHUNK   (NPG / TILE)                  // 8
#define NTRI     (NCHUNK * (NCHUNK + 1) / 2)   // 36
#define CTHREADS 256
#define NBLOCKS  ((NTRI + 1) * NB)             // 2368
#define JSLICE   16

// triangle tile decode tables (ic >= jc)
__device__ const signed char TIC[NTRI] =
    {0,1,1,2,2,2,3,3,3,3,4,4,4,4,4,5,5,5,5,5,5,
     6,6,6,6,6,6,6,7,7,7,7,7,7,7,7};
__device__ const signed char TJC[NTRI] =
    {0,0,1,0,1,2,0,1,2,3,0,1,2,3,4,0,1,2,3,4,5,
     0,1,2,3,4,5,6,0,1,2,3,4,5,6,7};

// bucket-partitioned points per batch: (x, y, z, |p|^2), tile-ordered in x
__device__ float4 g_pts[NB * NPG];
__device__ float  g_tmin[NB][NCHUNK];   // exact per-tile min x
__device__ float  g_tmax[NB][NCHUNK];   // exact per-tile max x

// partial slots — fully overwritten every launch (skipped tiles write 0)
__device__ float g_coll[NTRI * NB];     // 2304
__device__ float g_sb[NB][8];
__device__ unsigned int g_done = 0;

// ---------------- reduce helpers ----------------
__device__ __forceinline__ float wredSum(float v) {
#pragma unroll
    for (int o = 16; o; o >>= 1) v += __shfl_down_sync(0xffffffffu, v, o);
    return v;
}
__device__ __forceinline__ float wredMin(float v) {
#pragma unroll
    for (int o = 16; o; o >>= 1) v = fminf(v, __shfl_down_sync(0xffffffffu, v, o));
    return v;
}
__device__ __forceinline__ float wredMax(float v) {
#pragma unroll
    for (int o = 16; o; o >>= 1) v = fmaxf(v, __shfl_down_sync(0xffffffffu, v, o));
    return v;
}
__device__ __forceinline__ float blockSum(float v, float* sbuf) {
    const int lane = threadIdx.x & 31;
    const int wid  = threadIdx.x >> 5;
    v = wredSum(v);
    if (lane == 0) sbuf[wid] = v;
    __syncthreads();
    if (wid == 0) {
        v = (lane < 8) ? sbuf[lane] : 0.0f;
        v = wredSum(v);
        if (lane == 0) sbuf[0] = v;
    }
    __syncthreads();
    float r = sbuf[0];
    __syncthreads();
    return r;
}
__device__ __forceinline__ double blockSumD(double v, double* dbuf) {
    const int lane = threadIdx.x & 31;
    const int wid  = threadIdx.x >> 5;
#pragma unroll
    for (int o = 16; o; o >>= 1) v += __shfl_down_sync(0xffffffffu, v, o);
    if (lane == 0) dbuf[wid] = v;
    __syncthreads();
    if (wid == 0) {
        v = (lane < 8) ? dbuf[lane] : 0.0;
#pragma unroll
        for (int o = 16; o; o >>= 1) v += __shfl_down_sync(0xffffffffu, v, o);
        if (lane == 0) dbuf[0] = v;
    }
    __syncthreads();
    double r = dbuf[0];
    __syncthreads();
    return r;
}
__device__ __forceinline__ float sqrt_approx(float x) {
    float d; asm("sqrt.approx.f32 %0,%1;" : "=f"(d) : "f"(x)); return d;
}

// ---------------- bucket kernel: 256-bin counting partition by x -------------
// grid = NB, 256 threads. Produces g_pts tile-partitioned (rank = 256-bin
// counting order; exact per-tile min/max stored separately).
__global__ __launch_bounds__(256) void k_bucket(const float* __restrict__ pred)
{
    __shared__ unsigned hist[256];
    __shared__ unsigned base[256];
    __shared__ unsigned cnt[256];
    __shared__ unsigned wsum[8];

    const int b    = blockIdx.x;
    const int t    = threadIdx.x;
    const int lane = t & 31;
    const int wid  = t >> 5;

    hist[t] = 0;
    __syncthreads();

    // bin = monotone quantization of x over [-24, 24] into 256 bins
    int bins[4];
    float xs[4], ys[4], zs[4];
#pragma unroll
    for (int k = 0; k < 4; k++) {
        const int idx = t + k * 256;
        const float* p = pred + 3 * (size_t)(b * NPG + idx);
        xs[k] = p[0]; ys[k] = p[1]; zs[k] = p[2];
        int bin = (int)((xs[k] + 24.0f) * (256.0f / 48.0f));
        bin = min(max(bin, 0), 255);
        bins[k] = bin;
        atomicAdd(&hist[bin], 1u);
    }
    __syncthreads();

    // exclusive prefix over 256 bins (warp scan + warp-sum scan)
    const unsigned hv = hist[t];
    unsigned v = hv;
#pragma unroll
    for (int o = 1; o < 32; o <<= 1) {
        unsigned n = __shfl_up_sync(0xffffffffu, v, o);
        if (lane >= o) v += n;
    }
    if (lane == 31) wsum[wid] = v;
    __syncthreads();
    if (wid == 0) {
        unsigned s = (lane < 8) ? wsum[lane] : 0u;
#pragma unroll
        for (int o = 1; o < 8; o <<= 1) {
            unsigned n = __shfl_up_sync(0xffffffffu, s, o);
            if (lane >= o) s += n;
        }
        if (lane < 8) wsum[lane] = s;
    }
    __syncthreads();
    const unsigned incl = v + (wid > 0 ? wsum[wid - 1] : 0u);
    base[t] = incl - hv;     // exclusive prefix
    cnt[t]  = 0;
    __syncthreads();

    // scatter into partitioned order
#pragma unroll
    for (int k = 0; k < 4; k++) {
        const unsigned pos = base[bins[k]] + atomicAdd(&cnt[bins[k]], 1u);
        const float x = xs[k], y = ys[k], z = zs[k];
        g_pts[b * NPG + pos] = make_float4(x, y, z, fmaf(x, x, fmaf(y, y, z * z)));
    }
    __syncthreads();   // orders g_pts writes before same-block reads

    // exact per-tile min/max: warp w handles tile w (128 elements)
    {
        float mn =  1e30f, mx = -1e30f;
#pragma unroll
        for (int k = 0; k < 4; k++) {
            const float x = g_pts[b * NPG + wid * TILE + lane + 32 * k].x;
            mn = fminf(mn, x);
            mx = fmaxf(mx, x);
        }
        mn = wredMin(mn);
        mx = wredMax(mx);
        if (lane == 0) { g_tmin[b][wid] = mn; g_tmax[b][wid] = mx; }
    }
}

// ---------------- fused kernel (R13 structure, bucket-based prunes) ---------
// grid (NTRI+1, NB), 256 threads.
__global__ __launch_bounds__(CTHREADS) void k_fused(
    const float* __restrict__ pred,
    const float* __restrict__ tru,
    const float* __restrict__ org,
    const float* __restrict__ nfeat,
    float* __restrict__ out, int out_size)
{
    __shared__ float4 sj[TILE];
    __shared__ float  sred[8];
    __shared__ float  sq[16][8];
    __shared__ double dbuf[8];
    __shared__ bool   amLast;

    const int b  = blockIdx.y;
    const int bx = blockIdx.x;
    const int t  = threadIdx.x;
    const int lane = t & 31;
    const int wid  = t >> 5;

    if (bx < NTRI) {
        const int ic = TIC[bx];
        const int jc = TJC[bx];
        const float4* __restrict__ P = g_pts + (size_t)b * NPG;
        const int ibase = ic * TILE;
        const int jbase = jc * TILE;

        const float tmin_i = g_tmin[b][ic];

        // block-level exact prune: whole tile-pair has x-gap >= 2.9
        const bool skip = (ic != jc) && (tmin_i - g_tmax[b][jc] >= MIN_DIST);

        float S = 0.0f;
        if (!skip) {
            if (t < TILE) sj[t] = P[jbase + t];

            const int r   = lane;
            const int jlo = wid * JSLICE;

            float m2x[4], m2y[4], m2z[4], si[4];
#pragma unroll
            for (int k = 0; k < 4; k++) {
                const float4 pi = P[ibase + r + 32 * k];
                si[k]  = pi.w;
                m2x[k] = -2.0f * pi.x;
                m2y[k] = -2.0f * pi.y;
                m2z[k] = -2.0f * pi.z;
            }
            __syncthreads();

            // per-warp slice prune: exact slice max x via shfl reduce.
            // If tmin_i - sliceMax >= 2.9, every pair in the slice has
            // d >= dx >= 2.9 -> contributes exactly 0. Self-slices can never
            // satisfy this (own row's x is in both ranges -> gap <= 0).
            float sx = sj[jlo + (lane & (JSLICE - 1))].x;
#pragma unroll
            for (int o = 8; o; o >>= 1)
                sx = fmaxf(sx, __shfl_xor_sync(0xffffffffu, sx, o));
            const bool wskip = (tmin_i - sx >= MIN_DIST);

            float a = 0.0f;
            if (!wskip) {
                float acc[4] = {0.0f, 0.0f, 0.0f, 0.0f};
#pragma unroll
                for (int m = 0; m < JSLICE; m++) {
                    const float4 q = sj[jlo + m];
#pragma unroll
                    for (int k = 0; k < 4; k++) {
                        const float d2 = fmaf(m2x[k], q.x,
                                         fmaf(m2y[k], q.y,
                                         fmaf(m2z[k], q.z, si[k] + q.w)));
                        const float d  = sqrt_approx(d2);   // d2<0 -> NaN -> relu 0
                        const float e  = fmaxf(MIN_DIST - d, 0.0f);
                        acc[k] = fmaf(e, e, acc[k]);
                    }
                }
                a = (acc[0] + acc[1]) + (acc[2] + acc[3]);

                // diagonal: remove self-pairs (identical instruction sequence)
                if (ic == jc) {
#pragma unroll
                    for (int k = 0; k < 4; k++) {
                        const int i  = r + 32 * k;
                        const int jd = i - jlo;
                        if (jd >= 0 && jd < JSLICE) {
                            const float4 q = sj[i];
                            const float d2 = fmaf(m2x[k], q.x,
                                             fmaf(m2y[k], q.y,
                                             fmaf(m2z[k], q.z, si[k] + q.w)));
                            const float d  = sqrt_approx(d2);
                            const float e  = fmaxf(MIN_DIST - d, 0.0f);
                            a = fmaf(-e, e, a);
                        }
                    }
                }
            }

            S = blockSum(a, sred);
        }
        if (t == 0)
            g_coll[b * NTRI + bx] = skip ? 0.0f : ((ic != jc) ? 2.0f * S : S);
    } else {
        // ======================= stats =======================
        float px[4], py[4], pz[4], ox[4], oy[4], oz[4];
        float rsum = 0.0f;
#pragma unroll
        for (int k = 0; k < 4; k++) {
            const int idx = b * NPG + t + k * 256;
            const float* pp = pred + 3 * idx;
            const float* tt = tru  + 3 * idx;
            const float* oo = org  + 3 * idx;
            px[k] = pp[0]; py[k] = pp[1]; pz[k] = pp[2];
            const float dx = px[k] - tt[0];
            const float dy = py[k] - tt[1];
            const float dz = pz[k] - tt[2];
            rsum += dx * dx + dy * dy + dz * dz;
            ox[k] = oo[0]; oy[k] = oo[1]; oz[k] = oo[2];
        }

        float lv[14];
        lv[0]  = fminf(fminf(px[0], px[1]), fminf(px[2], px[3]));
        lv[1]  = fmaxf(fmaxf(px[0], px[1]), fmaxf(px[2], px[3]));
        lv[2]  = fminf(fminf(py[0], py[1]), fminf(py[2], py[3]));
        lv[3]  = fmaxf(fmaxf(py[0], py[1]), fmaxf(py[2], py[3]));
        lv[4]  = fminf(fminf(pz[0], pz[1]), fminf(pz[2], pz[3]));
        lv[5]  = fmaxf(fmaxf(pz[0], pz[1]), fmaxf(pz[2], pz[3]));
        lv[6]  = fminf(fminf(ox[0], ox[1]), fminf(ox[2], ox[3]));
        lv[7]  = fmaxf(fmaxf(ox[0], ox[1]), fmaxf(ox[2], ox[3]));
        lv[8]  = fminf(fminf(oy[0], oy[1]), fminf(oy[2], oy[3]));
        lv[9]  = fmaxf(fmaxf(oy[0], oy[1]), fmaxf(oy[2], oy[3]));
        lv[10] = fminf(fminf(oz[0], oz[1]), fminf(oz[2], oz[3]));
        lv[11] = fmaxf(fmaxf(oz[0], oz[1]), fmaxf(oz[2], oz[3]));
        lv[12] = pz[0] + pz[1] + pz[2] + pz[3];
        lv[13] = rsum;

#pragma unroll
        for (int i = 0; i < 14; i++) {
            float v;
            if (i < 12) v = (i & 1) ? wredMax(lv[i]) : wredMin(lv[i]);
            else        v = wredSum(lv[i]);
            if (lane == 0) sq[i][wid] = v;
        }
        __syncthreads();
        if (t < 14) {
            float a = sq[t][0];
            const bool isMin = (t < 12) && !(t & 1);
            const bool isMax = (t < 12) &&  (t & 1);
#pragma unroll
            for (int w = 1; w < 8; w++) {
                const float u = sq[t][w];
                a = isMin ? fminf(a, u) : (isMax ? fmaxf(a, u) : (a + u));
            }
            sq[t][0] = a;
        }
        __syncthreads();

        const float OMNZ = sq[10][0], OMXZ = sq[11][0];
        const float zr   = __fsub_rn(OMXZ, OMNZ);
        const float thlo = __fadd_rn(OMNZ, __fmul_rn(0.15f, zr));
        const float thhi = __fsub_rn(OMXZ, __fmul_rn(0.15f, zr));

        float esum = 0.0f, ecnt = 0.0f;
#pragma unroll
        for (int k = 0; k < 4; k++) {
            const bool m = (oz[k] <= thlo) || (oz[k] >= thhi);
            if (m) {
                const float dx = px[k] - ox[k];
                const float dy = py[k] - oy[k];
                const float dz = pz[k] - oz[k];
                esum += dx * dx + dy * dy + dz * dz;
                ecnt += 1.0f;
            }
        }
        esum = wredSum(esum);
        ecnt = wredSum(ecnt);
        if (lane == 0) { sq[14][wid] = esum; sq[15][wid] = ecnt; }
        __syncthreads();

        if (t == 0) {
            float ES = 0.0f, EC = 0.0f;
#pragma unroll
            for (int w = 0; w < 8; w++) { ES += sq[14][w]; EC += sq[15][w]; }

            const float pdx = sq[1][0] - sq[0][0];
            const float pdy = sq[3][0] - sq[2][0];
            const float pdz = sq[5][0] - sq[4][0];
            const float odx = sq[7][0] - sq[6][0];
            const float ody = sq[9][0] - sq[8][0];
            const float odz = OMXZ - OMNZ;
            const float rx = (pdx - odx) / (odx + 1e-8f);
            const float ry = (pdy - ody) / (ody + 1e-8f);
            const float rz = (pdz - odz) / (odz + 1e-8f);
            const float xy_pen = fmaxf(rx - 0.02f, 0.0f) + fmaxf(ry - 0.02f, 0.0f);
            const float z_pen  = fmaxf(rz, 0.0f);

            const float zcom  = sq[12][0] * (1.0f / 1024.0f);
            const float znorm = (zcom - sq[4][0]) / ((sq[5][0] - sq[4][0]) + 1e-8f);
            const float v = nfeat[(size_t)b * NPG * NFEA + (NFEA - 3)];
            const float target = (v > 0.0f) ? 0.6f : 0.4f;
            const float dvz = znorm - target;
            const float contrib = (fabsf(v) >= 1e-6f) ? dvz * dvz : 0.0f;

            g_sb[b][0] = sq[13][0];
            g_sb[b][1] = ES;
            g_sb[b][2] = EC;
            g_sb[b][3] = xy_pen + 2.0f * z_pen;
            g_sb[b][4] = contrib;
        }
        __syncthreads();
    }

    // ======================= last-block finalize =======================
    __threadfence();
    if (t == 0) {
        const unsigned int ret = atomicAdd(&g_done, 1u);
        amLast = (ret == (unsigned)(NBLOCKS - 1));
    }
    __syncthreads();

    if (amLast) {
        __threadfence();

        double cs = 0.0;
#pragma unroll
        for (int k = 0; k < 9; k++) cs += (double)g_coll[t + k * 256];   // 2304
        const double COLL = blockSumD(cs, dbuf);

        double r = 0.0, e = 0.0, c = 0.0, vo = 0.0, f = 0.0;
        if (t < NB) {
            r  = (double)g_sb[t][0];
            e  = (double)g_sb[t][1];
            c  = (double)g_sb[t][2];
            vo = (double)g_sb[t][3];
            f  = (double)g_sb[t][4];
        }
        const double RSUM = blockSumD(r,  dbuf);
        const double ESUM = blockSumD(e,  dbuf);
        const double ECNT = blockSumD(c,  dbuf);
        const double VSUM = blockSumD(vo, dbuf);
        const double FSUM = blockSumD(f,  dbuf);

        if (t == 0) {
            const double recon  = RSUM / (double)(NB * NPG * 3);
            const double volume = VSUM / (double)NB;
            const double elec   = ESUM / (ECNT * 3.0);
            const double coll   = COLL / ((double)NB * (double)NPG * (double)(NPG - 1));
            const double field  = FSUM / (double)NB;
            const double total  = 1.0 * recon + 10.0 * volume + 50.0 * elec
                                + 5.0 * coll + 2.0 * field;
            double vals[6] = { total, recon, volume, elec, coll, field };
            for (int i = 0; i < 6 && i < out_size; i++) out[i] = (float)vals[i];
            g_done = 0;   // reset for next graph replay
        }
    }
}

extern "C" void kernel_launch(void* const* d_in, const int* in_sizes, int n_in,
                              void* d_out, int out_size)
{
    int coord_idx[3]; int n_coord = 0;
    int nf_idx = -1, bv_idx = -1;
    for (int i = 0; i < n_in; i++) {
        if (in_sizes[i] == NB * NPG * 3) { if (n_coord < 3) coord_idx[n_coord] = i; n_coord++; }
        else if (in_sizes[i] == NB * NPG * NFEA) nf_idx = i;
        else if (in_sizes[i] == NB * NPG) bv_idx = i;
    }

    const float *pred, *tru, *org, *nf;
    if (n_coord == 3 && nf_idx >= 0) {
        if (bv_idx >= 0 && bv_idx < coord_idx[0]) {
            org  = (const float*)d_in[coord_idx[0]];
            pred = (const float*)d_in[coord_idx[1]];
            tru  = (const float*)d_in[coord_idx[2]];
        } else {
            pred = (const float*)d_in[coord_idx[0]];
            tru  = (const float*)d_in[coord_idx[1]];
            org  = (const float*)d_in[coord_idx[2]];
        }
        nf = (const float*)d_in[nf_idx];
    } else {
        pred = (const float*)d_in[0];
        tru  = (const float*)d_in[1];
        org  = (const float*)d_in[2];
        nf   = (const float*)d_in[3];
    }

    k_bucket<<<NB, 256>>>(pred);
    k_fused<<<dim3(NTRI + 1, NB), CTHREADS>>>(pred, tru, org, nf,
                                              (float*)d_out, out_size);
}